// round 16
// baseline (speedup 1.0000x reference)
#include <cuda_runtime.h>

// linear_sig: depth-3 path signature (B=2048, T=128, C=8) + linear head (584 -> 10)
//
// R16: ILP-over-TLP restructure. One warp owns a WHOLE row and runs both
// T-halves' recurrences interleaved in one loop (two independent dependence
// chains per warp -> warp nearly always issue-eligible despite low occupancy;
// warp supply is hard-capped at 43% so TLP can't rise). Chen combine is now
// warp-local (dump -> syncwarp -> combine): no __syncthreads anywhere, no
// cross-warp coupling. 64-thread blocks (2 rows), 1024 blocks. Step math
// unchanged (8x fma.rn.f32x2 S3 per half, scalar aux); coalesced epilogue,
// one warp does all 10 outputs of its own row.
//   Chen (A then B): S1c=S1a+S1b; S2c=S2a+S2b+S1a(i)S1b(j);
//   S3c=S3a+S3b+S2a(i,j)S1b(l)+S1a(i)S2b(j,l)

constexpr int TT      = 128;
constexpr int CC      = 8;
constexpr int NOUT    = 10;
constexpr int SIGDIM  = 584;      // 8 + 64 + 512
constexpr int WARPS   = 2;        // rows per block
constexpr int THREADS = WARPS * 32;   // 64
constexpr int STEPS   = 64;       // increments per half
constexpr int NQ      = 19;       // ceil(584/32)
constexpr int BUF     = TT * CC;  // 1024 floats per warp (both halves)

using ull = unsigned long long;

__device__ __forceinline__ ull dup2(float x) {
    ull r; asm("mov.b64 %0,{%1,%1};" : "=l"(r) : "f"(x)); return r;
}
__device__ __forceinline__ float2 upk(ull v) {
    float2 f; asm("mov.b64 {%0,%1},%2;" : "=f"(f.x), "=f"(f.y) : "l"(v)); return f;
}
__device__ __forceinline__ void f2fma(ull& acc, ull a, ull b) {
    asm("fma.rn.f32x2 %0,%1,%2,%0;" : "+l"(acc) : "l"(a), "l"(b));
}

// State slot layout (712 floats): [0..7]=S1, [8..71]=S2(i*8+j), [72+r*20+k]=S3[r][k]
// Linear sig index idx -> slot offset: idx<72 -> idx; else idx + 4*((idx-72)>>4).
__device__ __forceinline__ void dump20(float* f, int lane, int i0, int j0,
                                       float S1, float S20, float S21,
                                       const float* S3) {
    if ((lane & 3) == 0) f[i0] = S1;
    *(float2*)(f + 8 + i0 * 8 + j0) = make_float2(S20, S21);
    float* c3 = f + 72 + lane * 20;
    *(float4*)(c3)      = make_float4(S3[0],  S3[1],  S3[2],  S3[3]);
    *(float4*)(c3 + 4)  = make_float4(S3[4],  S3[5],  S3[6],  S3[7]);
    *(float4*)(c3 + 8)  = make_float4(S3[8],  S3[9],  S3[10], S3[11]);
    *(float4*)(c3 + 12) = make_float4(S3[12], S3[13], S3[14], S3[15]);
}

// In-place: (state A) <- A then B, B read from slot f.
__device__ __forceinline__ void combine20(const float* f, int i0, int j0, int lane,
                                          float& S1, float& S20, float& S21,
                                          float* S3) {
    const float* c3 = f + 72 + lane * 20;
    #pragma unroll
    for (int l = 0; l < 8; l++) {
        float s1bl = f[l];
        S3[l]     += c3[l]     + S20 * s1bl + S1 * f[8 + j0 * 8 + l];
        S3[8 + l] += c3[8 + l] + S21 * s1bl + S1 * f[8 + (j0 + 1) * 8 + l];
    }
    S20 += f[8 + i0 * 8 + j0]     + S1 * f[j0];
    S21 += f[8 + i0 * 8 + j0 + 1] + S1 * f[j0 + 1];
    S1  += f[i0];
}

__global__ __launch_bounds__(THREADS, 8)
void sig_linear_kernel(const float* __restrict__ X,
                       const float* __restrict__ W,
                       const float* __restrict__ Bv,
                       float* __restrict__ out, int nB)
{
    __shared__ __align__(16) float sx[WARPS * BUF];  // per-warp dx staging / state slot

    const int wib  = threadIdx.x >> 5;
    const int lane = threadIdx.x & 31;
    const int row  = blockIdx.x * WARPS + wib;

    const int i0 = lane >> 2;
    const int j0 = (lane & 3) << 1;

    float* sxw = sx + wib * BUF;

    // Stage all 128 dx slots (slot s = x[min(s+1,127)]-x[s]; slot 127 -> 0).
    {
        const float* xb = X + (size_t)row * (TT * CC);
        #pragma unroll
        for (int s = lane; s < TT; s += 32) {
            int g1 = (s + 1 < TT) ? s + 1 : TT - 1;
            float4 a0 = *(const float4*)(xb + s * 8);
            float4 a1 = *(const float4*)(xb + s * 8 + 4);
            float4 b0 = *(const float4*)(xb + g1 * 8);
            float4 b1 = *(const float4*)(xb + g1 * 8 + 4);
            *(float4*)(sxw + s * 8)     = make_float4(b0.x - a0.x, b0.y - a0.y,
                                                      b0.z - a0.z, b0.w - a0.w);
            *(float4*)(sxw + s * 8 + 4) = make_float4(b1.x - a1.x, b1.y - a1.y,
                                                      b1.z - a1.z, b1.w - a1.w);
        }
    }
    __syncwarp();

    // Two independent half-recurrences, interleaved for ILP.
    float S1a = 0.f, S1ha = 0.f, S20a = 0.f, S21a = 0.f;
    float S1b = 0.f, S1hb = 0.f, S20b = 0.f, S21b = 0.f;
    ull S3pa[8], S3pb[8];
    #pragma unroll
    for (int m = 0; m < 8; m++) { S3pa[m] = 0ull; S3pb[m] = 0ull; }

    {
        const float* bufA = sxw;
        const float* bufB = sxw + STEPS * CC;
        #pragma unroll 2
        for (int s = 0; s < STEPS; s++) {
            const float* rwA = bufA + s * 8;
            const float* rwB = bufB + s * 8;
            ulonglong2 qaA = *(const ulonglong2*)(rwA);
            ulonglong2 qbA = *(const ulonglong2*)(rwA + 4);
            float2 djA = *(const float2*)(rwA + j0);
            float  diA = rwA[i0];
            ulonglong2 qaB = *(const ulonglong2*)(rwB);
            ulonglong2 qbB = *(const ulonglong2*)(rwB + 4);
            float2 djB = *(const float2*)(rwB + j0);
            float  diB = rwB[i0];

            // --- half A ---
            float uA   = fmaf(diA, 1.f / 6.f, S1ha);
            float vA   = fmaf(diA, 0.5f, S1a);
            float t30A = fmaf(djA.x, uA, S20a);
            float t31A = fmaf(djA.y, uA, S21a);
            ull T0A = dup2(t30A);
            ull T1A = dup2(t31A);
            f2fma(S3pa[0], qaA.x, T0A);
            f2fma(S3pa[1], qaA.y, T0A);
            f2fma(S3pa[2], qbA.x, T0A);
            f2fma(S3pa[3], qbA.y, T0A);
            f2fma(S3pa[4], qaA.x, T1A);
            f2fma(S3pa[5], qaA.y, T1A);
            f2fma(S3pa[6], qbA.x, T1A);
            f2fma(S3pa[7], qbA.y, T1A);
            S20a = fmaf(djA.x, vA, S20a);
            S21a = fmaf(djA.y, vA, S21a);
            S1a += diA;
            S1ha = fmaf(diA, 0.5f, S1ha);

            // --- half B (independent chain) ---
            float uB   = fmaf(diB, 1.f / 6.f, S1hb);
            float vB   = fmaf(diB, 0.5f, S1b);
            float t30B = fmaf(djB.x, uB, S20b);
            float t31B = fmaf(djB.y, uB, S21b);
            ull T0B = dup2(t30B);
            ull T1B = dup2(t31B);
            f2fma(S3pb[0], qaB.x, T0B);
            f2fma(S3pb[1], qaB.y, T0B);
            f2fma(S3pb[2], qbB.x, T0B);
            f2fma(S3pb[3], qbB.y, T0B);
            f2fma(S3pb[4], qaB.x, T1B);
            f2fma(S3pb[5], qaB.y, T1B);
            f2fma(S3pb[6], qbB.x, T1B);
            f2fma(S3pb[7], qbB.y, T1B);
            S20b = fmaf(djB.x, vB, S20b);
            S21b = fmaf(djB.y, vB, S21b);
            S1b += diB;
            S1hb = fmaf(diB, 0.5f, S1hb);
        }
    }

    // Unpack both halves' S3.
    float S3a[16], S3b[16];
    #pragma unroll
    for (int m = 0; m < 8; m++) {
        float2 fa = upk(S3pa[m]);
        S3a[2 * m] = fa.x; S3a[2 * m + 1] = fa.y;
        float2 fb = upk(S3pb[m]);
        S3b[2 * m] = fb.x; S3b[2 * m + 1] = fb.y;
    }

    __syncwarp();   // staging reads done -> warp's buffer reusable as state slot

    // Warp-local Chen combine: dump B, combine into A, dump combined.
    dump20(sxw, lane, i0, j0, S1b, S20b, S21b, S3b);
    __syncwarp();
    combine20(sxw, i0, j0, lane, S1a, S20a, S21a, S3a);
    __syncwarp();
    dump20(sxw, lane, i0, j0, S1a, S20a, S21a, S3a);
    __syncwarp();

    // Coalesced epilogue (this warp's row, all 10 outputs).
    {
        float sv[NQ];
        #pragma unroll
        for (int q = 0; q < NQ; q++) {
            int idx = q * 32 + lane;
            if (idx < SIGDIM) {
                int off = (idx < 72) ? idx : idx + (((idx - 72) >> 4) << 2);
                sv[q] = sxw[off];
            } else {
                sv[q] = 0.f;
            }
        }

        float* orow = out + (size_t)row * NOUT;
        for (int n = 0; n < NOUT; n++) {
            const float* wr = W + (size_t)n * SIGDIM;
            float pa = 0.f;
            #pragma unroll
            for (int q = 0; q < NQ - 1; q++)
                pa = fmaf(sv[q], wr[q * 32 + lane], pa);   // coalesced LDG.32
            {
                int idx = (NQ - 1) * 32 + lane;
                float wv = (idx < SIGDIM) ? wr[idx] : 0.f;
                pa = fmaf(sv[NQ - 1], wv, pa);
            }
            #pragma unroll
            for (int off = 16; off; off >>= 1)
                pa += __shfl_xor_sync(0xffffffffu, pa, off);
            if (lane == 0) orow[n] = pa + Bv[n];
        }
    }
}

extern "C" void kernel_launch(void* const* d_in, const int* in_sizes, int n_in,
                              void* d_out, int out_size) {
    const float* X  = (const float*)d_in[0];
    const float* W  = (const float*)d_in[1];
    const float* b  = (const float*)d_in[2];
    float* out      = (float*)d_out;
    int nB = in_sizes[0] / (TT * CC);                 // 2048
    int grid = (nB + WARPS - 1) / WARPS;              // 1024 blocks
    sig_linear_kernel<<<grid, THREADS>>>(X, W, b, out, nB);
}

// round 17
// speedup vs baseline: 1.1179x; 1.1179x over previous
#include <cuda_runtime.h>

// linear_sig: depth-3 path signature (B=2048, T=128, C=8) + linear head (584 -> 10)
//
// R17 = R15 (best: split-2 via Chen, pointer-walk software pipeline, 8x
// fma.rn.f32x2 S3 step) + float4-vectorized epilogue. Aligned 4-chunks of the
// linear sig index never cross an S3 16-block boundary, so the slot-offset map
// (idx + 4*((idx-72)>>4)) is affine per chunk: signature reads become 5
// LDS.128 and each output's W reads become 5 LDG.128 (epilogue ~215 -> ~140
// slots/warp). R16 (ILP-over-TLP) regressed and is reverted.

constexpr int TT      = 128;
constexpr int CC      = 8;
constexpr int NOUT    = 10;
constexpr int SIGDIM  = 584;      // 8 + 64 + 512
constexpr int WARPS   = 4;        // 2 row-pairs per block
constexpr int PAIRS   = WARPS / 2;
constexpr int THREADS = WARPS * 32;   // 128
constexpr int STEPS   = 64;       // increments per half
constexpr int NCH     = SIGDIM / 4;   // 146 aligned 4-chunks
constexpr int BUF     = STEPS * CC;   // 512 floats per half-buffer

using ull = unsigned long long;

__device__ __forceinline__ ull dup2(float x) {
    ull r; asm("mov.b64 %0,{%1,%1};" : "=l"(r) : "f"(x)); return r;
}
__device__ __forceinline__ float2 upk(ull v) {
    float2 f; asm("mov.b64 {%0,%1},%2;" : "=f"(f.x), "=f"(f.y) : "l"(v)); return f;
}
__device__ __forceinline__ void f2fma(ull& acc, ull a, ull b) {
    asm("fma.rn.f32x2 %0,%1,%2,%0;" : "+l"(acc) : "l"(a), "l"(b));
}

// State slot layout (712 floats): [0..7]=S1, [8..71]=S2(i*8+j), [72+r*20+k]=S3[r][k]
// Linear sig index idx -> slot offset: idx<72 -> idx; else idx + 4*((idx-72)>>4).
__device__ __forceinline__ void dump20(float* f, int lane, int i0, int j0,
                                       float S1, float S20, float S21,
                                       const float* S3) {
    if ((lane & 3) == 0) f[i0] = S1;
    *(float2*)(f + 8 + i0 * 8 + j0) = make_float2(S20, S21);
    float* c3 = f + 72 + lane * 20;
    *(float4*)(c3)      = make_float4(S3[0],  S3[1],  S3[2],  S3[3]);
    *(float4*)(c3 + 4)  = make_float4(S3[4],  S3[5],  S3[6],  S3[7]);
    *(float4*)(c3 + 8)  = make_float4(S3[8],  S3[9],  S3[10], S3[11]);
    *(float4*)(c3 + 12) = make_float4(S3[12], S3[13], S3[14], S3[15]);
}

// In-place: (state A) <- A then B, B read from slot f.
__device__ __forceinline__ void combine20(const float* f, int i0, int j0, int lane,
                                          float& S1, float& S20, float& S21,
                                          float* S3) {
    const float* c3 = f + 72 + lane * 20;
    #pragma unroll
    for (int l = 0; l < 8; l++) {
        float s1bl = f[l];
        S3[l]     += c3[l]     + S20 * s1bl + S1 * f[8 + j0 * 8 + l];
        S3[8 + l] += c3[8 + l] + S21 * s1bl + S1 * f[8 + (j0 + 1) * 8 + l];
    }
    S20 += f[8 + i0 * 8 + j0]     + S1 * f[j0];
    S21 += f[8 + i0 * 8 + j0 + 1] + S1 * f[j0 + 1];
    S1  += f[i0];
}

__global__ __launch_bounds__(THREADS, 8)
void sig_linear_kernel(const float* __restrict__ X,
                       const float* __restrict__ W,
                       const float* __restrict__ Bv,
                       float* __restrict__ out, int nB)
{
    // Flat staging buffer + 8-float pad so the last dummy prefetch (slot 64 of
    // the final half-buffer) stays in-bounds. Aliased as state slots later.
    __shared__ __align__(16) float sx[PAIRS * 2 * BUF + 8];

    const int wib  = threadIdx.x >> 5;
    const int lane = threadIdx.x & 31;
    const int pair = wib >> 1;
    const int half = wib & 1;                  // 0 = combiner
    const int row  = blockIdx.x * PAIRS + pair;

    const int i0 = lane >> 2;
    const int j0 = (lane & 3) << 1;
    const int t0 = half ? STEPS : 0;

    float* sxw = sx + (pair * 2 + half) * BUF;

    // Stage dx (branchless): slot s holds x[min(g+1,127)]-x[g]; pad slot -> 0.
    {
        const float* xb = X + (size_t)row * (TT * CC);
        #pragma unroll
        for (int s = lane; s < STEPS; s += 32) {
            int g  = t0 + s;
            int g1 = (g + 1 < TT - 1) ? g + 1 : TT - 1;
            float4 a0 = *(const float4*)(xb + g * 8);
            float4 a1 = *(const float4*)(xb + g * 8 + 4);
            float4 b0 = *(const float4*)(xb + g1 * 8);
            float4 b1 = *(const float4*)(xb + g1 * 8 + 4);
            *(float4*)(sxw + s * 8)     = make_float4(b0.x - a0.x, b0.y - a0.y,
                                                      b0.z - a0.z, b0.w - a0.w);
            *(float4*)(sxw + s * 8 + 4) = make_float4(b1.x - a1.x, b1.y - a1.y,
                                                      b1.z - a1.z, b1.w - a1.w);
        }
    }
    __syncwarp();

    float S1 = 0.f, S1h = 0.f;            // S1[i], S1[i]/2
    float S20 = 0.f, S21 = 0.f;
    ull S3p[8];
    #pragma unroll
    for (int m = 0; m < 8; m++) S3p[m] = 0ull;

    {
        // Software pipeline, pure pointer walk: compute step s while loading
        // s+1. Iteration s=63 prefetches slot 64 (valid smem, discarded).
        const float* rw = sxw;
        ulonglong2 qa = *(const ulonglong2*)(rw);
        ulonglong2 qb = *(const ulonglong2*)(rw + 4);
        float2 dj = *(const float2*)(rw + j0);
        float  di = rw[i0];

        #pragma unroll 4
        for (int s = 0; s < STEPS; s++) {
            const float* rn = rw + 8;
            ulonglong2 qa_n = *(const ulonglong2*)(rn);
            ulonglong2 qb_n = *(const ulonglong2*)(rn + 4);
            float2 dj_n = *(const float2*)(rn + j0);
            float  di_n = rn[i0];

            float u   = fmaf(di, 1.f / 6.f, S1h);          // OLD S1 baked in
            float v   = fmaf(di, 0.5f, S1);
            float t30 = fmaf(dj.x, u, S20);                // OLD S2
            float t31 = fmaf(dj.y, u, S21);
            ull T0 = dup2(t30);
            ull T1 = dup2(t31);

            f2fma(S3p[0], qa.x, T0);
            f2fma(S3p[1], qa.y, T0);
            f2fma(S3p[2], qb.x, T0);
            f2fma(S3p[3], qb.y, T0);
            f2fma(S3p[4], qa.x, T1);
            f2fma(S3p[5], qa.y, T1);
            f2fma(S3p[6], qb.x, T1);
            f2fma(S3p[7], qb.y, T1);

            S20 = fmaf(dj.x, v, S20);
            S21 = fmaf(dj.y, v, S21);
            S1 += di;
            S1h = fmaf(di, 0.5f, S1h);

            qa = qa_n; qb = qb_n; dj = dj_n; di = di_n;
            rw = rn;
        }
    }

    float S3[16];
    #pragma unroll
    for (int m = 0; m < 8; m++) {
        float2 f = upk(S3p[m]);
        S3[2 * m] = f.x; S3[2 * m + 1] = f.y;
    }

    __syncthreads();   // staging reads done -> smem reusable as state slots

    float* fslot = sx + pair * 2 * BUF;   // 712 of the pair's 1024 staging floats

    if (half == 1) dump20(fslot, lane, i0, j0, S1, S20, S21, S3);
    __syncthreads();

    if (half == 0) {
        combine20(fslot, i0, j0, lane, S1, S20, S21, S3);
        __syncwarp();                  // all combine reads done before overwrite
        dump20(fslot, lane, i0, j0, S1, S20, S21, S3);
    }
    __syncthreads();

    // Vectorized coalesced epilogue: warp w -> pair (w>>1), outputs [(w&1)*5,+5).
    // Lane holds chunk c = 32q+lane (4 consecutive sig values; chunks never
    // cross an S3 16-block, so the slot map is affine per chunk).
    {
        const int p    = wib >> 1;
        const int rowE = blockIdx.x * PAIRS + p;
        const float* f = sx + p * 2 * BUF;
        float4 sv4[5];
        #pragma unroll
        for (int q = 0; q < 5; q++) {
            int c = q * 32 + lane;
            if (c < NCH) {
                int lin = 4 * c;
                int off = (lin < 72) ? lin : lin + (((lin - 72) >> 4) << 2);
                sv4[q] = *(const float4*)(f + off);
            } else {
                sv4[q] = make_float4(0.f, 0.f, 0.f, 0.f);
            }
        }

        float* orow = out + (size_t)rowE * NOUT;
        const int n0 = (wib & 1) * 5;
        for (int q5 = 0; q5 < 5; q5++) {
            int n = n0 + q5;
            const float* wr = W + (size_t)n * SIGDIM;
            float pa = 0.f;
            #pragma unroll
            for (int q = 0; q < 5; q++) {
                int c = q * 32 + lane;
                if (c < NCH) {                       // only q=4 actually predicated
                    float4 w4 = *(const float4*)(wr + 4 * c);   // coalesced LDG.128
                    pa = fmaf(sv4[q].x, w4.x, pa);
                    pa = fmaf(sv4[q].y, w4.y, pa);
                    pa = fmaf(sv4[q].z, w4.z, pa);
                    pa = fmaf(sv4[q].w, w4.w, pa);
                }
            }
            #pragma unroll
            for (int off = 16; off; off >>= 1)
                pa += __shfl_xor_sync(0xffffffffu, pa, off);
            if (lane == 0) orow[n] = pa + Bv[n];
        }
    }
}

extern "C" void kernel_launch(void* const* d_in, const int* in_sizes, int n_in,
                              void* d_out, int out_size) {
    const float* X  = (const float*)d_in[0];
    const float* W  = (const float*)d_in[1];
    const float* b  = (const float*)d_in[2];
    float* out      = (float*)d_out;
    int nB = in_sizes[0] / (TT * CC);                 // 2048
    int grid = (nB + PAIRS - 1) / PAIRS;              // 1024 blocks
    sig_linear_kernel<<<grid, THREADS>>>(X, W, b, out, nB);
}